// round 16
// baseline (speedup 1.0000x reference)
#include <cuda_runtime.h>
#include <math.h>

// Problem constants (fixed by the reference):
//   S=2048, B=128, K=64, D=256, T=6, MAX_LEN=2048, out row = T+D = 262 floats
#define S_DIM 2048
#define B_DIM 128
#define K_DIM 64
#define D_DIM 256
#define T_DIM 6
#define ROW_LEN (T_DIM + D_DIM)   // 262
#define LOG_2PI 1.8378770664093453f

// Precomputed per-d polynomial coefficients, layout [j][d] for coalesced loads.
// M[j*256+d]: coefficients of {x^2, x*y, y^2, x, y, 1} for output channel d.
// (bias b[d] is folded into the constant term.)
__device__ float g_M[6 * D_DIM];

// ---------------------------------------------------------------------------
// Kernel 1: fold K away.  lw[s,b,k] is quadratic in (x,y):
//   quad_k = ia*dx^2 + 2*ib*dx*dy + ic*dy^2   (inv covariance from A A^T)
//   lw_k   = -0.5*(quad_k + log(det) + 2*log(2*pi))
// Expanding dx = x - mx, dy = y - my gives per-key coefficients C[k][0..5].
// Then M[d][j] = sum_k W[d,k] * C[k][j]  (D x 6 instead of D x K).
// ---------------------------------------------------------------------------
__global__ void precompute_M_kernel(const float* __restrict__ means,
                                    const float* __restrict__ A,
                                    const float* __restrict__ W,
                                    const float* __restrict__ bias) {
    __shared__ float C[K_DIM][6];
    const int t = threadIdx.x;   // 256 threads

    if (t < K_DIM) {
        const float a00 = A[t * 4 + 0];
        const float a01 = A[t * 4 + 1];
        const float a10 = A[t * 4 + 2];
        const float a11 = A[t * 4 + 3];
        // cov = A A^T (symmetric 2x2)
        const float c00 = a00 * a00 + a01 * a01;
        const float c01 = a00 * a10 + a01 * a11;
        const float c11 = a10 * a10 + a11 * a11;
        const float det = c00 * c11 - c01 * c01;
        const float ia =  c11 / det;
        const float ib = -c01 / det;
        const float ic =  c00 / det;
        const float mx = means[t * 2 + 0];
        const float my = means[t * 2 + 1];
        C[t][0] = -0.5f * ia;                       // x^2
        C[t][1] = -ib;                              // x*y
        C[t][2] = -0.5f * ic;                       // y^2
        C[t][3] = ia * mx + ib * my;                // x
        C[t][4] = ib * mx + ic * my;                // y
        C[t][5] = -0.5f * (ia * mx * mx + 2.0f * ib * mx * my + ic * my * my
                           + logf(det) + 2.0f * LOG_2PI);   // const
    }
    __syncthreads();

    // t == d here (256 threads, D=256). W is (D,K) row-major.
    float m0 = 0.f, m1 = 0.f, m2 = 0.f, m3 = 0.f, m4 = 0.f, m5 = 0.f;
#pragma unroll 8
    for (int k = 0; k < K_DIM; k++) {
        const float w = W[t * K_DIM + k];
        m0 = fmaf(w, C[k][0], m0);
        m1 = fmaf(w, C[k][1], m1);
        m2 = fmaf(w, C[k][2], m2);
        m3 = fmaf(w, C[k][3], m3);
        m4 = fmaf(w, C[k][4], m4);
        m5 = fmaf(w, C[k][5], m5);
    }
    m5 += bias[t];

    g_M[0 * D_DIM + t] = m0;
    g_M[1 * D_DIM + t] = m1;
    g_M[2 * D_DIM + t] = m2;
    g_M[3 * D_DIM + t] = m3;
    g_M[4 * D_DIM + t] = m4;
    g_M[5 * D_DIM + t] = m5;
}

// ---------------------------------------------------------------------------
// Kernel 2: produce the full (S, B, 262) output.
//   grid = (S, B/B_CHUNK); block = 288 threads (9 warps).
//   Thread t:  t <  6   -> copies traj_feats column t
//              6<=t<262 -> owns output channel d = t-6; keeps M[d][*], and
//                          (M5 + pe[s,d]) in REGISTERS; 5 FMAs per element.
//   xy for the 64 rows of this chunk staged in shared (broadcast reads).
//   Stores: contiguous 262-float rows -> fully coalesced STG.32.
// ---------------------------------------------------------------------------
#define B_CHUNK 64
#define TPB 288

__global__ __launch_bounds__(TPB)
void emit_kernel(const float* __restrict__ traj,
                 const float* __restrict__ xy,
                 const float* __restrict__ pe,
                 float* __restrict__ out) {
    const int s  = blockIdx.x;
    const int b0 = blockIdx.y * B_CHUNK;
    const int t  = threadIdx.x;

    __shared__ float sxy[2 * B_CHUNK];
    if (t < 2 * B_CHUNK) {
        sxy[t] = xy[(unsigned)(s * B_DIM + b0) * 2u + t];
    }

    // Per-channel constants in registers.
    float M0 = 0.f, M1 = 0.f, M2 = 0.f, M3 = 0.f, M4 = 0.f, M5p = 0.f;
    const bool is_emb = (t >= T_DIM) && (t < ROW_LEN);
    if (is_emb) {
        const int d = t - T_DIM;
        M0 = g_M[0 * D_DIM + d];
        M1 = g_M[1 * D_DIM + d];
        M2 = g_M[2 * D_DIM + d];
        M3 = g_M[3 * D_DIM + d];
        M4 = g_M[4 * D_DIM + d];
        M5p = g_M[5 * D_DIM + d] + pe[(unsigned)s * D_DIM + d];
    }
    __syncthreads();

    const unsigned row0 = (unsigned)s * B_DIM + b0;

#pragma unroll 4
    for (int i = 0; i < B_CHUNK; i++) {
        const unsigned row = row0 + i;
        float v;
        if (t < T_DIM) {
            v = traj[row * (unsigned)T_DIM + t];
        } else {
            const float x = sxy[2 * i + 0];
            const float y = sxy[2 * i + 1];
            // v = M0 x^2 + M1 xy + M2 y^2 + M3 x + M4 y + M5p   (5 FMAs)
            float t1 = fmaf(M0, x, M3);
            t1 = fmaf(M1, y, t1);
            float t2 = fmaf(M2, y, M4);
            v = fmaf(t1, x, M5p);
            v = fmaf(t2, y, v);
        }
        if (t < ROW_LEN) {
            out[row * (unsigned)ROW_LEN + t] = v;
        }
    }
}

// ---------------------------------------------------------------------------
// Inputs (metadata order, per reference setup_inputs):
//   0: traj_feats (S*B*T)   1: xy_coords (S*B*2)   2: means (K*2)
//   3: A (K*2*2)            4: W (D*K)             5: b (D)
//   6: pe (MAX_LEN*1*D)
// Output: float32, S*B*(T+D)
// ---------------------------------------------------------------------------
extern "C" void kernel_launch(void* const* d_in, const int* in_sizes, int n_in,
                              void* d_out, int out_size) {
    const float* traj  = (const float*)d_in[0];
    const float* xy    = (const float*)d_in[1];
    const float* means = (const float*)d_in[2];
    const float* A     = (const float*)d_in[3];
    const float* W     = (const float*)d_in[4];
    const float* bias  = (const float*)d_in[5];
    const float* pe    = (const float*)d_in[6];
    float* out = (float*)d_out;

    precompute_M_kernel<<<1, D_DIM>>>(means, A, W, bias);

    dim3 grid(S_DIM, B_DIM / B_CHUNK);
    emit_kernel<<<grid, TPB>>>(traj, xy, pe, out);
}

// round 17
// speedup vs baseline: 2.0228x; 2.0228x over previous
#include <cuda_runtime.h>
#include <math.h>
#include <stdint.h>

// Problem constants (fixed by the reference):
//   S=2048, B=128, K=64, D=256, T=6, MAX_LEN=2048, out row = T+D = 262 floats
#define S_DIM 2048
#define B_DIM 128
#define K_DIM 64
#define D_DIM 256
#define T_DIM 6
#define ROW_LEN (T_DIM + D_DIM)   // 262
#define LOG_2PI 1.8378770664093453f

// Precomputed per-d polynomial coefficients, layout [j][d] for coalesced loads.
// g_M[j*256+d]: coefficients of {x^2, x*y, y^2, x, y, 1} for output channel d.
// (bias b[d] is folded into the constant term.)
__device__ float g_M[6 * D_DIM];

// ---------------------------------------------------------------------------
// Kernel 1: fold K away.  lw[s,b,k] is quadratic in (x,y):
//   quad_k = ia*dx^2 + 2*ib*dx*dy + ic*dy^2   (inv covariance from A A^T)
//   lw_k   = -0.5*(quad_k + log(det) + 2*log(2*pi))
// Expanding dx = x - mx, dy = y - my gives per-key coefficients C[k][0..5].
// Then M[d][j] = sum_k W[d,k] * C[k][j]  (D x 6 instead of D x K).
//
// Parallelized: 8 blocks x 256 threads. Each block owns 32 d-channels; each
// channel's K=64 reduction is split over 8 lanes (8 k's each, one fully
// outstanding load batch) and combined with a shfl butterfly.
// ---------------------------------------------------------------------------
__global__ void precompute_M_kernel(const float* __restrict__ means,
                                    const float* __restrict__ A,
                                    const float* __restrict__ W,
                                    const float* __restrict__ bias) {
    __shared__ float C[K_DIM][6];
    const int t = threadIdx.x;   // 256 threads

    if (t < K_DIM) {
        const float a00 = A[t * 4 + 0];
        const float a01 = A[t * 4 + 1];
        const float a10 = A[t * 4 + 2];
        const float a11 = A[t * 4 + 3];
        // cov = A A^T (symmetric 2x2)
        const float c00 = a00 * a00 + a01 * a01;
        const float c01 = a00 * a10 + a01 * a11;
        const float c11 = a10 * a10 + a11 * a11;
        const float det = c00 * c11 - c01 * c01;
        const float ia =  c11 / det;
        const float ib = -c01 / det;
        const float ic =  c00 / det;
        const float mx = means[t * 2 + 0];
        const float my = means[t * 2 + 1];
        C[t][0] = -0.5f * ia;                       // x^2
        C[t][1] = -ib;                              // x*y
        C[t][2] = -0.5f * ic;                       // y^2
        C[t][3] = ia * mx + ib * my;                // x
        C[t][4] = ib * mx + ic * my;                // y
        C[t][5] = -0.5f * (ia * mx * mx + 2.0f * ib * mx * my + ic * my * my
                           + logf(det) + 2.0f * LOG_2PI);   // const
    }
    __syncthreads();

    const int d_local = t >> 3;                 // 0..31
    const int part    = t & 7;                  // 0..7  (8-aligned lane groups)
    const int d       = blockIdx.x * 32 + d_local;

    float m0 = 0.f, m1 = 0.f, m2 = 0.f, m3 = 0.f, m4 = 0.f, m5 = 0.f;
#pragma unroll
    for (int j = 0; j < 8; j++) {
        const int k = part * 8 + j;
        const float w = W[d * K_DIM + k];
        m0 = fmaf(w, C[k][0], m0);
        m1 = fmaf(w, C[k][1], m1);
        m2 = fmaf(w, C[k][2], m2);
        m3 = fmaf(w, C[k][3], m3);
        m4 = fmaf(w, C[k][4], m4);
        m5 = fmaf(w, C[k][5], m5);
    }
    // butterfly reduce across the 8 lanes of this d (groups are 8-aligned in lane id)
#pragma unroll
    for (int off = 4; off >= 1; off >>= 1) {
        m0 += __shfl_xor_sync(0xffffffffu, m0, off);
        m1 += __shfl_xor_sync(0xffffffffu, m1, off);
        m2 += __shfl_xor_sync(0xffffffffu, m2, off);
        m3 += __shfl_xor_sync(0xffffffffu, m3, off);
        m4 += __shfl_xor_sync(0xffffffffu, m4, off);
        m5 += __shfl_xor_sync(0xffffffffu, m5, off);
    }
    if (part == 0) {
        g_M[0 * D_DIM + d] = m0;
        g_M[1 * D_DIM + d] = m1;
        g_M[2 * D_DIM + d] = m2;
        g_M[3 * D_DIM + d] = m3;
        g_M[4 * D_DIM + d] = m4;
        g_M[5 * D_DIM + d] = m5 + bias[d];
    }
}

// ---------------------------------------------------------------------------
// Kernel 2: produce the full (S, B, 262) output.
//   grid = (S, B/B_CHUNK); block = 256 threads (8 warps).
//   Phase A: stage the whole 32-row x 262-float chunk into SMEM:
//     - threads t<192 copy traj (fully coalesced: traj[row0*6 + t]) into the
//       interleaved row slots (conflict-free: bank = t%32)
//     - every thread owns emb channel d = t; M[d][*] and (M5+pe[s,d]) live in
//       registers; 5 FMAs + 1 STS per element, xy via broadcast LDS.
//   Phase B: ONE cp.async.bulk (33,536 B, 16B-aligned both ends) SMEM->GMEM.
//   Store issue is offloaded to the bulk-copy engine; the kernel streams at
//   DRAM write bandwidth instead of STG-issue/latency rate.
// ---------------------------------------------------------------------------
#define B_CHUNK 32
#define CHUNK_BYTES (B_CHUNK * ROW_LEN * 4)   // 33536, multiple of 16

__global__ __launch_bounds__(256)
void emit_kernel(const float* __restrict__ traj,
                 const float* __restrict__ xy,
                 const float* __restrict__ pe,
                 float* __restrict__ out) {
    __shared__ __align__(16) float buf[B_CHUNK * ROW_LEN];
    __shared__ float sxy[2 * B_CHUNK];

    const int s  = blockIdx.x;
    const int b0 = blockIdx.y * B_CHUNK;
    const int t  = threadIdx.x;
    const unsigned row0 = (unsigned)s * B_DIM + b0;   // multiple of 32 -> even

    if (t < 2 * B_CHUNK) {
        sxy[t] = xy[row0 * 2u + t];
    }
    if (t < B_CHUNK * T_DIM) {   // 192 coalesced traj loads
        buf[(t / T_DIM) * ROW_LEN + (t % T_DIM)] = traj[row0 * (unsigned)T_DIM + t];
    }

    // Per-channel constants in registers (d = t; 256 threads = 256 channels).
    const int d = t;
    const float M0  = g_M[0 * D_DIM + d];
    const float M1  = g_M[1 * D_DIM + d];
    const float M2  = g_M[2 * D_DIM + d];
    const float M3  = g_M[3 * D_DIM + d];
    const float M4  = g_M[4 * D_DIM + d];
    const float M5p = g_M[5 * D_DIM + d] + pe[(unsigned)s * D_DIM + d];

    __syncthreads();

#pragma unroll 8
    for (int i = 0; i < B_CHUNK; i++) {
        const float x = sxy[2 * i + 0];
        const float y = sxy[2 * i + 1];
        // v = M0 x^2 + M1 xy + M2 y^2 + M3 x + M4 y + M5p   (5 FMAs)
        float t1 = fmaf(M0, x, M3);
        t1 = fmaf(M1, y, t1);
        float t2 = fmaf(M2, y, M4);
        float v = fmaf(t1, x, M5p);
        v = fmaf(t2, y, v);
        buf[i * ROW_LEN + T_DIM + t] = v;
    }

    __syncthreads();

    if (t == 0) {
        // order generic-proxy STS before the async-proxy bulk read
        asm volatile("fence.proxy.async.shared::cta;" ::: "memory");
        uint32_t saddr = (uint32_t)__cvta_generic_to_shared(buf);
        const float* gdst = out + (size_t)row0 * ROW_LEN;
        int nbytes = CHUNK_BYTES;
        asm volatile(
            "cp.async.bulk.global.shared::cta.bulk_group [%0], [%1], %2;"
            :: "l"(gdst), "r"(saddr), "r"(nbytes) : "memory");
        asm volatile("cp.async.bulk.commit_group;" ::: "memory");
        // must not let SMEM be freed while the bulk engine still reads it
        asm volatile("cp.async.bulk.wait_group 0;" ::: "memory");
    }
}

// ---------------------------------------------------------------------------
// Inputs (metadata order, per reference setup_inputs):
//   0: traj_feats (S*B*T)   1: xy_coords (S*B*2)   2: means (K*2)
//   3: A (K*2*2)            4: W (D*K)             5: b (D)
//   6: pe (MAX_LEN*1*D)
// Output: float32, S*B*(T+D)
// ---------------------------------------------------------------------------
extern "C" void kernel_launch(void* const* d_in, const int* in_sizes, int n_in,
                              void* d_out, int out_size) {
    const float* traj  = (const float*)d_in[0];
    const float* xy    = (const float*)d_in[1];
    const float* means = (const float*)d_in[2];
    const float* A     = (const float*)d_in[3];
    const float* W     = (const float*)d_in[4];
    const float* bias  = (const float*)d_in[5];
    const float* pe    = (const float*)d_in[6];
    float* out = (float*)d_out;

    precompute_M_kernel<<<8, 256>>>(means, A, W, bias);

    dim3 grid(S_DIM, B_DIM / B_CHUNK);
    emit_kernel<<<grid, 256>>>(traj, xy, pe, out);
}